// round 5
// baseline (speedup 1.0000x reference)
#include <cuda_runtime.h>
#include <cuda_bf16.h>

#define SEQ   4096
#define DIM   512
#define DIM1  513
#define PI_F  3.14159265358979f

// Output-vectorized concat: each thread produces one aligned float4 of the
// flat [B*S*513] output. Mapping: flat idx -> (row, col); col<512 copies
// input, col==512 computes the positional channel.
__global__ __launch_bounds__(256) void pe_concat_kernel(
    const float* __restrict__ in,
    const int*   __restrict__ lengths,
    float*       __restrict__ out,
    int n4)
{
    int i4 = blockIdx.x * blockDim.x + threadIdx.x;
    if (i4 >= n4) return;

    int base = i4 * 4;          // flat output element index (< 2^26, int ok)
    int r = base / DIM1;        // row = b*4096 + s  (const-div -> mulhi)
    int c = base - r * DIM1;    // column in [0, 513)

    float v[4];
#pragma unroll
    for (int j = 0; j < 4; j++) {
        float val;
        if (c < DIM) {
            val = __ldg(in + r * DIM + c);
        } else {
            // positional channel for row r
            int b = r >> 12;                 // row / 4096
            int s = r & (SEQ - 1);           // row % 4096
            float fl   = (float)__ldg(lengths + b);
            float safe = fmaxf(fl, 1.0f);
            val = ((float)s < fl) ? __cosf(((float)s / safe) * PI_F) : 0.0f;
        }
        v[j] = val;
        if (++c == DIM1) { c = 0; ++r; }
    }

    float4 o;
    o.x = v[0]; o.y = v[1]; o.z = v[2]; o.w = v[3];
    reinterpret_cast<float4*>(out)[i4] = o;
}

extern "C" void kernel_launch(void* const* d_in, const int* in_sizes, int n_in,
                              void* d_out, int out_size)
{
    const float* in      = (const float*)d_in[0];   // [16, 4096, 512] f32
    const int*   lengths = (const int*)  d_in[1];   // [16] i32
    float*       out     = (float*)d_out;           // [16, 4096, 513] f32

    int n4 = out_size / 4;                          // out_size = 33,619,968 (div by 4)
    int threads = 256;
    int blocks  = (n4 + threads - 1) / threads;
    pe_concat_kernel<<<blocks, threads>>>(in, lengths, out, n4);
}